// round 2
// baseline (speedup 1.0000x reference)
#include <cuda_runtime.h>
#include <float.h>

// WOS: weighted order statistic over unfolded 3x3 patches (+/- mirrored), per
// output channel. O(D^2) rank-by-counting instead of sorting.
//
// Shapes (fixed by problem): x (8,3,64,64) f32; mask (16,54); weight (16,54);
// bias (16,1); out flat = y[(n,nc)] at n*16+nc, n = b*4096 + h*64 + w.

#define NCH   16
#define DTOT  54
#define DHALF 27
#define TOL   1e-6f

__global__ __launch_bounds__(512, 1)
void wos_kernel(const float* __restrict__ x,
                const float* __restrict__ mask,
                const float* __restrict__ weight,
                const float* __restrict__ bias,
                float* __restrict__ out)
{
    __shared__ float msk[NCH * DTOT];     // mask, per-nc
    __shared__ float wgs[NCH * DTOT];     // gated weights: w>tol ? w : 0
    __shared__ float ptile[3][3][34];     // [c][kh][col] halo tile for 32 pixels

    const int tid = threadIdx.x + threadIdx.y * 16;   // x = nc (16), y = pixel (32)

    // ---- cooperative loads ----
    for (int e = tid; e < NCH * DTOT; e += 512) {
        msk[e] = mask[e];
        float w = weight[e];
        wgs[e] = (w > TOL) ? w : 0.0f;
    }

    const int n0  = blockIdx.x * 32;      // 32 consecutive pixels: same (b,h)
    const int b   = n0 >> 12;
    const int rem = n0 & 4095;
    const int h   = rem >> 6;
    const int w0  = rem & 63;             // 0 or 32

    for (int e = tid; e < 3 * 3 * 34; e += 512) {
        int c   = e / 102;                // 102 = 3*34
        int r   = (e / 34) % 3;
        int col = e % 34;
        int gr  = h - 1 + r;
        int gc  = w0 - 1 + col;
        float v = 0.0f;
        if ((unsigned)gr < 64u && (unsigned)gc < 64u)
            v = x[((b * 3 + c) * 64 + gr) * 64 + gc];
        ptile[c][r][col] = v;
    }
    __syncthreads();

    const int nc = threadIdx.x;
    const int py = threadIdx.y;
    const int n  = n0 + py;
    const int mb = nc * DTOT;

    // ---- build mx[54] = [p, -p] + mask[nc] in registers ----
    float mx[DTOT];
    #pragma unroll
    for (int c = 0; c < 3; c++)
        #pragma unroll
        for (int r = 0; r < 3; r++)
            #pragma unroll
            for (int kw = 0; kw < 3; kw++) {
                int d = c * 9 + r * 3 + kw;
                float p = ptile[c][r][py + kw];
                mx[d]          = p + msk[mb + d];
                mx[d + DHALF]  = msk[mb + d + DHALF] - p;
            }

    const float biasv = bias[nc];
    float selMin = FLT_MAX;
    float fbMax  = -FLT_MAX;
    int found = 0, anynz = 0;

    // ---- counting selection: j tiled by 9, i streamed over all 54 ----
    #pragma unroll
    for (int t = 0; t < 6; t++) {
        float acc[9];
        #pragma unroll
        for (int jj = 0; jj < 9; jj++)
            acc[jj] = wgs[mb + t * 9 + jj];   // inclusive cum starts at own gated weight

        #pragma unroll
        for (int i = 0; i < DTOT; i++) {
            float wi = wgs[mb + i];
            float mi = mx[i];
            #pragma unroll
            for (int jj = 0; jj < 9; jj++) {
                int j = t * 9 + jj;
                if (i == j) continue;         // compile-time skip
                // stable-sort tie break: i<j ties sort before j
                bool b4 = (i < j) ? (mi >= mx[j]) : (mi > mx[j]);
                if (b4) acc[jj] += wi;        // predicated FADD
            }
        }

        #pragma unroll
        for (int jj = 0; jj < 9; jj++) {
            int j = t * 9 + jj;
            float wj = wgs[mb + j];
            if (wj > 0.0f) {
                anynz = 1;
                float vj = mx[j];
                fbMax = fmaxf(fbMax, vj);
                if (acc[jj] <= biasv) {
                    found = 1;
                    selMin = fminf(selMin, vj);
                }
            }
        }
    }

    float res = found ? selMin : (anynz ? fbMax : 0.0f);
    out[n * NCH + nc] = res;   // flat reinterpret layout: coalesced per warp
}

extern "C" void kernel_launch(void* const* d_in, const int* in_sizes, int n_in,
                              void* d_out, int out_size) {
    const float* x      = (const float*)d_in[0];
    const float* mask   = (const float*)d_in[1];
    const float* weight = (const float*)d_in[2];
    const float* bias   = (const float*)d_in[3];
    float* out = (float*)d_out;

    // 32768 pixels / 32 per block = 1024 blocks; block = 16 nc x 32 pixels
    wos_kernel<<<1024, dim3(16, 32)>>>(x, mask, weight, bias, out);
}

// round 3
// speedup vs baseline: 1.3570x; 1.3570x over previous
#include <cuda_runtime.h>
#include <float.h>

// WOS: weighted order statistic over unfolded 3x3 patches (+/- mirrored), per
// output channel. O(D^2) rank-by-counting; compare+accumulate emitted as
// FSETP + predicated FADD via inline PTX (avoids the FSEL the compiler
// otherwise inserts, which made the kernel ALU-pipe bound).

#define NCH   16
#define DTOT  54
#define DHALF 27
#define TOL   1e-6f

// acc += w  if mi >  mxj   (strict: i > j in original index order)
__device__ __forceinline__ void cadd_gt(float& acc, float mi, float mxj, float w) {
    asm volatile("{\n\t"
        ".reg .pred p;\n\t"
        "setp.gt.f32 p, %1, %2;\n\t"
        "@p add.f32 %0, %0, %3;\n\t"
        "}" : "+f"(acc) : "f"(mi), "f"(mxj), "f"(w));
}
// acc += w  if mi >= mxj   (ties win: i < j in original index order)
__device__ __forceinline__ void cadd_ge(float& acc, float mi, float mxj, float w) {
    asm volatile("{\n\t"
        ".reg .pred p;\n\t"
        "setp.ge.f32 p, %1, %2;\n\t"
        "@p add.f32 %0, %0, %3;\n\t"
        "}" : "+f"(acc) : "f"(mi), "f"(mxj), "f"(w));
}

__global__ __launch_bounds__(512, 1)
void wos_kernel(const float* __restrict__ x,
                const float* __restrict__ mask,
                const float* __restrict__ weight,
                const float* __restrict__ bias,
                float* __restrict__ out)
{
    __shared__ float msk[NCH * DTOT];     // mask, per-nc
    __shared__ float wgs[NCH * DTOT];     // gated weights: w>tol ? w : 0
    __shared__ float ptile[3][3][34];     // [c][kh][col] halo tile for 32 pixels

    const int tid = threadIdx.x + threadIdx.y * 16;   // x = nc (16), y = pixel (32)

    // ---- cooperative loads ----
    for (int e = tid; e < NCH * DTOT; e += 512) {
        msk[e] = mask[e];
        float w = weight[e];
        wgs[e] = (w > TOL) ? w : 0.0f;
    }

    const int n0  = blockIdx.x * 32;      // 32 consecutive pixels: same (b,h)
    const int b   = n0 >> 12;
    const int rem = n0 & 4095;
    const int h   = rem >> 6;
    const int w0  = rem & 63;             // 0 or 32

    for (int e = tid; e < 3 * 3 * 34; e += 512) {
        int c   = e / 102;                // 102 = 3*34
        int r   = (e / 34) % 3;
        int col = e % 34;
        int gr  = h - 1 + r;
        int gc  = w0 - 1 + col;
        float v = 0.0f;
        if ((unsigned)gr < 64u && (unsigned)gc < 64u)
            v = x[((b * 3 + c) * 64 + gr) * 64 + gc];
        ptile[c][r][col] = v;
    }
    __syncthreads();

    const int nc = threadIdx.x;
    const int py = threadIdx.y;
    const int n  = n0 + py;
    const int mb = nc * DTOT;

    // ---- build mx[54] = [p, -p] + mask[nc] in registers ----
    float mx[DTOT];
    #pragma unroll
    for (int c = 0; c < 3; c++)
        #pragma unroll
        for (int r = 0; r < 3; r++)
            #pragma unroll
            for (int kw = 0; kw < 3; kw++) {
                int d = c * 9 + r * 3 + kw;
                float p = ptile[c][r][py + kw];
                mx[d]          = p + msk[mb + d];
                mx[d + DHALF]  = msk[mb + d + DHALF] - p;
            }

    const float biasv = bias[nc];
    float selMin = FLT_MAX;
    float fbMax  = -FLT_MAX;
    int found = 0, anynz = 0;

    // ---- counting selection: j tiled by 9, i streamed over all 54 ----
    #pragma unroll
    for (int t = 0; t < 6; t++) {
        float acc[9];
        #pragma unroll
        for (int jj = 0; jj < 9; jj++)
            acc[jj] = wgs[mb + t * 9 + jj];   // inclusive cum starts at own gated weight

        #pragma unroll
        for (int i = 0; i < DTOT; i++) {
            float wi = wgs[mb + i];
            float mi = mx[i];
            #pragma unroll
            for (int jj = 0; jj < 9; jj++) {
                int j = t * 9 + jj;
                if (i == j) continue;         // compile-time skip
                // stable-sort tie break: i<j ties sort before j
                if (i < j) cadd_ge(acc[jj], mi, mx[j], wi);
                else       cadd_gt(acc[jj], mi, mx[j], wi);
            }
        }

        #pragma unroll
        for (int jj = 0; jj < 9; jj++) {
            int j = t * 9 + jj;
            float wj = wgs[mb + j];
            if (wj > 0.0f) {
                anynz = 1;
                float vj = mx[j];
                fbMax = fmaxf(fbMax, vj);
                if (acc[jj] <= biasv) {
                    found = 1;
                    selMin = fminf(selMin, vj);
                }
            }
        }
    }

    float res = found ? selMin : (anynz ? fbMax : 0.0f);
    out[n * NCH + nc] = res;   // flat reinterpret layout: coalesced per warp
}

extern "C" void kernel_launch(void* const* d_in, const int* in_sizes, int n_in,
                              void* d_out, int out_size) {
    const float* x      = (const float*)d_in[0];
    const float* mask   = (const float*)d_in[1];
    const float* weight = (const float*)d_in[2];
    const float* bias   = (const float*)d_in[3];
    float* out = (float*)d_out;

    // 32768 pixels / 32 per block = 1024 blocks; block = 16 nc x 32 pixels
    wos_kernel<<<1024, dim3(16, 32)>>>(x, mask, weight, bias, out);
}

// round 6
// speedup vs baseline: 1.4311x; 1.0546x over previous
#include <cuda_runtime.h>
#include <float.h>

// WOS: weighted order statistic, O(D^2/2) symmetric rank-by-counting.
// Each unordered pair (i<j) compared ONCE: b = mx_i >= mx_j; the loser's
// accumulator receives the winner's weight (exclusive "sorted-before" cumsum),
// emitted as FSETP + two complementary predicated FADDs (3 issues/pair).

#define NCH   16
#define DTOT  54
#define DHALF 27
#define TOL   1e-6f
#define JT    18          // j-tile size (3 tiles)
#define PX    8           // pixels per block

// i < j guaranteed by iteration order: ties (>=) put i before j (stable argsort).
__device__ __forceinline__ void pair_update(float& accj, float& acci,
                                            float mi, float mj,
                                            float wi, float wj) {
    asm volatile("{\n\t"
        ".reg .pred p;\n\t"
        "setp.ge.f32 p, %2, %3;\n\t"
        "@p  add.f32 %0, %0, %4;\n\t"
        "@!p add.f32 %1, %1, %5;\n\t"
        "}" : "+f"(accj), "+f"(acci)
            : "f"(mi), "f"(mj), "f"(wi), "f"(wj));
}

__global__ __launch_bounds__(128, 3)
void wos_kernel(const float* __restrict__ x,
                const float* __restrict__ mask,
                const float* __restrict__ weight,
                const float* __restrict__ bias,
                float* __restrict__ out)
{
    __shared__ float msk[NCH * DTOT];       // mask per nc
    __shared__ float wgs[NCH * DTOT];       // gated weights: w>tol ? w : 0
    __shared__ float ptile[3][3][PX + 2];   // [c][kh][col] halo for PX pixels

    const int tid = threadIdx.x + threadIdx.y * 16;   // x = nc(16), y = pixel(PX)

    for (int e = tid; e < NCH * DTOT; e += 128) {
        msk[e] = mask[e];
        float w = weight[e];
        wgs[e] = (w > TOL) ? w : 0.0f;
    }

    const int n0  = blockIdx.x * PX;        // PX consecutive pixels, same (b,h)
    const int b   = n0 >> 12;
    const int rem = n0 & 4095;
    const int h   = rem >> 6;
    const int w0  = rem & 63;

    for (int e = tid; e < 3 * 3 * (PX + 2); e += 128) {
        int c   = e / (3 * (PX + 2));
        int r   = (e / (PX + 2)) % 3;
        int col = e % (PX + 2);
        int gr  = h - 1 + r;
        int gc  = w0 - 1 + col;
        float v = 0.0f;
        if ((unsigned)gr < 64u && (unsigned)gc < 64u)
            v = x[((b * 3 + c) * 64 + gr) * 64 + gc];
        ptile[c][r][col] = v;
    }
    __syncthreads();

    const int nc = threadIdx.x;
    const int py = threadIdx.y;
    const int n  = n0 + py;
    const int mb = nc * DTOT;

    // ---- mx[54] = [p, -p] + mask[nc] ----
    float mx[DTOT];
    #pragma unroll
    for (int c = 0; c < 3; c++)
        #pragma unroll
        for (int r = 0; r < 3; r++)
            #pragma unroll
            for (int kw = 0; kw < 3; kw++) {
                int d = c * 9 + r * 3 + kw;
                float p = ptile[c][r][py + kw];
                mx[d]         = p + msk[mb + d];
                mx[d + DHALF] = msk[mb + d + DHALF] - p;
            }

    // ---- inclusive accumulators start at own gated weight ----
    float acc[DTOT];
    #pragma unroll
    for (int d = 0; d < DTOT; d++)
        acc[d] = wgs[mb + d];

    // ---- symmetric pair loop, j tiled by JT ----
    #pragma unroll
    for (int t = 0; t < DTOT / JT; t++) {
        const int J0 = t * JT;
        float wj[JT];
        #pragma unroll
        for (int jj = 0; jj < JT; jj++)
            wj[jj] = wgs[mb + J0 + jj];

        #pragma unroll
        for (int i = 0; i < J0 + JT; i++) {
            float mi = mx[i];
            float wi = (i >= J0) ? wj[i - J0] : wgs[mb + i];  // compile-time pick
            #pragma unroll
            for (int jj = 0; jj < JT; jj++) {
                int j = J0 + jj;
                if (j > i)
                    pair_update(acc[j], acc[i], mi, mx[j], wi, wj[jj]);
            }
        }
    }

    // ---- selection epilogue ----
    const float biasv = bias[nc];
    float selMin = FLT_MAX;
    float fbMax  = -FLT_MAX;
    int found = 0, anynz = 0;

    #pragma unroll
    for (int j = 0; j < DTOT; j++) {
        float wjv = wgs[mb + j];
        if (wjv > 0.0f) {
            anynz = 1;
            float vj = mx[j];
            fbMax = fmaxf(fbMax, vj);
            if (acc[j] <= biasv) {
                found = 1;
                selMin = fminf(selMin, vj);
            }
        }
    }

    float res = found ? selMin : (anynz ? fbMax : 0.0f);
    out[n * NCH + nc] = res;    // flat layout: coalesced per warp
}

extern "C" void kernel_launch(void* const* d_in, const int* in_sizes, int n_in,
                              void* d_out, int out_size) {
    const float* x      = (const float*)d_in[0];
    const float* mask   = (const float*)d_in[1];
    const float* weight = (const float*)d_in[2];
    const float* bias   = (const float*)d_in[3];
    float* out = (float*)d_out;

    // 32768 pixels / 8 per block = 4096 blocks; block = 16 nc x 8 pixels
    wos_kernel<<<4096, dim3(16, PX)>>>(x, mask, weight, bias, out);
}